// round 9
// baseline (speedup 1.0000x reference)
#include <cuda_runtime.h>
#include <cuda_fp16.h>

#define NQ 4
#define DIM 16
#define NPARAMS 36

typedef unsigned int u32;

// fp16-split of the 16x16 unitary, row-major [k][j]
__device__ __half g_Uh_r[DIM][DIM];
__device__ __half g_Ul_r[DIM][DIM];
__device__ __half g_Uh_i[DIM][DIM];
__device__ __half g_Ul_i[DIM][DIM];

// Per-lane pre-packed B fragments: [lane][16] u32
__device__ u32 g_Bfrag[32][16];

// ---------------------------------------------------------------------------
// Build U(params): threads 0..15 each own one COLUMN of U.
// RY(t1)·RZ(t2)·RY(t3) fused into one complex 2x2 gate.
// ---------------------------------------------------------------------------
__global__ void build_U_kernel(const float* __restrict__ params) {
    const int c = threadIdx.x;

    if (c < DIM) {
        float P[NPARAMS];
#pragma unroll
        for (int i = 0; i < NPARAMS; i++) P[i] = params[i];

        float ur[DIM], ui[DIM];
#pragma unroll
        for (int j = 0; j < DIM; j++) { ur[j] = (j == c) ? 1.0f : 0.0f; ui[j] = 0.0f; }

        int off = 0;
#pragma unroll
        for (int layer = 0; layer < 3; layer++) {
#pragma unroll
            for (int wi = 0; wi < NQ; wi++) {
                const int bit = 1 << (NQ - 1 - wi);
                const float t1 = 0.5f * P[off], t2 = 0.5f * P[off + 1], t3 = 0.5f * P[off + 2];
                off += 3;
                float A, B_, C, D, cf, sf;
                __sincosf(t1 + t3, &B_, &A);
                __sincosf(t1 - t3, &D, &C);
                __sincosf(t2, &sf, &cf);
                const float p = A * cf, q = B_ * cf, u = C * sf, w = D * sf;
#pragma unroll
                for (int r = 0; r < DIM; r++) {
                    if (r & bit) continue;
                    const int r1 = r | bit;
                    const float v0r = ur[r], v0i = ui[r], v1r = ur[r1], v1i = ui[r1];
                    ur[r]  =  p * v0r + u * v0i - q * v1r - w * v1i;
                    ui[r]  = -u * v0r + p * v0i + w * v1r - q * v1i;
                    ur[r1] =  q * v0r - w * v0i + p * v1r - u * v1i;
                    ui[r1] =  w * v0r + q * v0i + u * v1r + p * v1i;
                }
            }
            // CNOT ring = row swaps
#pragma unroll
            for (int g = 0; g < NQ; g++) {
                const int cb = 1 << (NQ - 1 - g);
                const int tb = 1 << (NQ - 1 - ((g + 1) & 3));
#pragma unroll
                for (int r = 0; r < DIM; r++) {
                    if ((r & cb) && !(r & tb)) {
                        const int r1 = r | tb;
                        float t;
                        t = ur[r]; ur[r] = ur[r1]; ur[r1] = t;
                        t = ui[r]; ui[r] = ui[r1]; ui[r1] = t;
                    }
                }
            }
        }

#pragma unroll
        for (int k = 0; k < DIM; k++) {
            __half h;
            h = __float2half_rn(ur[k]);
            g_Uh_r[k][c] = h;
            g_Ul_r[k][c] = __float2half_rn(ur[k] - __half2float(h));
            h = __float2half_rn(ui[k]);
            g_Uh_i[k][c] = h;
            g_Ul_i[k][c] = __float2half_rn(ui[k] - __half2float(h));
        }
    }

    __syncthreads();

    // Pack per-lane B fragments (lane = g*4 + t)
    {
        const int lane = threadIdx.x;
        const int g = lane >> 2, t = lane & 3;
        u32 frag[16];
#pragma unroll
        for (int nt = 0; nt < 2; nt++) {
            const int kk = 8 * nt + g;
            frag[0  + 2 * nt] = *(const u32*)&g_Uh_r[kk][2 * t];
            frag[1  + 2 * nt] = *(const u32*)&g_Uh_r[kk][2 * t + 8];
            frag[4  + 2 * nt] = *(const u32*)&g_Uh_i[kk][2 * t];
            frag[5  + 2 * nt] = *(const u32*)&g_Uh_i[kk][2 * t + 8];
            frag[8  + 2 * nt] = *(const u32*)&g_Ul_r[kk][2 * t];
            frag[9  + 2 * nt] = *(const u32*)&g_Ul_r[kk][2 * t + 8];
            frag[12 + 2 * nt] = *(const u32*)&g_Ul_i[kk][2 * t];
            frag[13 + 2 * nt] = *(const u32*)&g_Ul_i[kk][2 * t + 8];
        }
        uint4* dst = (uint4*)g_Bfrag[lane];
#pragma unroll
        for (int v = 0; v < 4; v++)
            dst[v] = make_uint4(frag[4 * v], frag[4 * v + 1], frag[4 * v + 2], frag[4 * v + 3]);
    }
}

// ---------------- helpers ----------------
__device__ __forceinline__ u32 pack_f16x2(float lo, float hi) {
    const __half2 h2 = __floats2half2_rn(lo, hi);
    return *(const u32*)&h2;
}
__device__ __forceinline__ void f16_split(float lo, float hi, u32& h, u32& l) {
    const __half2 h2 = __floats2half2_rn(lo, hi);
    const float2 f = __half22float2(h2);
    const __half2 l2 = __floats2half2_rn(lo - f.x, hi - f.y);
    h = *(const u32*)&h2;
    l = *(const u32*)&l2;
}
__device__ __forceinline__ void mma_f16(float c[4], const u32 a[4], const u32 b[2]) {
    asm volatile(
        "mma.sync.aligned.m16n8k16.row.col.f32.f16.f16.f32 "
        "{%0,%1,%2,%3}, {%4,%5,%6,%7}, {%8,%9}, {%0,%1,%2,%3};"
        : "+f"(c[0]), "+f"(c[1]), "+f"(c[2]), "+f"(c[3])
        : "r"(a[0]), "r"(a[1]), "r"(a[2]), "r"(a[3]), "r"(b[0]), "r"(b[1]));
}
__device__ __forceinline__ void ldsm_x4(u32 r[4], u32 saddr) {
    asm volatile("ldmatrix.sync.aligned.m8n8.x4.shared.b16 {%0,%1,%2,%3}, [%4];"
                 : "=r"(r[0]), "=r"(r[1]), "=r"(r[2]), "=r"(r[3]) : "r"(saddr));
}

// ---------------------------------------------------------------------------
// Main kernel: 2 ADJACENT patches/thread via 2x LDG.128; warp = 64 patches
// = 4 MMA tiles. ldsm stays inside the tile loop (register economy).
// ---------------------------------------------------------------------------
__global__ void __launch_bounds__(256) quanv_kernel(
    const float* __restrict__ x, float* __restrict__ out, int npatch)
{
    // staging: 8 warps x 64 patch slots x 80B (Ph[16 f16] @0, Pl @32, pad)
    __shared__ __align__(16) unsigned char stage[8 * 64 * 80];

    const int tid  = threadIdx.x;
    const int lane = tid & 31;
    const int wrp  = tid >> 5;
    const int g    = lane >> 2;
    const int t    = lane & 3;

    const int warpbase = blockIdx.x * 512 + wrp * 64;
    unsigned char* const ws = stage + wrp * (64 * 80);

    const float HPI = 1.5707963267948966f;

    // ---- pair addressing: pair e covers patches 2e, 2e+1 (same image rows) ----
    const int npair = npatch >> 1;
    int e = (warpbase >> 1) + lane;
    if (e >= npair) e = npair - 1;
    const int b   = e / 98;
    const int rem = e - b * 98;
    const int r   = rem / 7;
    const int c2  = rem - r * 7;
    const float* base = x + b * 784 + r * 56 + c2 * 4;

    const float4 rowT = *(const float4*)(base);        // top row:    p0:(x,y) p1:(z,w)
    const float4 rowB = *(const float4*)(base + 28);   // bottom row: p0:(x,y) p1:(z,w)

    // ---- psi0 + fp16 split + stage, per patch (slot = 2*lane+pp) ----
#pragma unroll
    for (int pp = 0; pp < 2; pp++) {
        const float px0 = pp ? rowT.z : rowT.x;
        const float px1 = pp ? rowT.w : rowT.y;
        const float px2 = pp ? rowB.z : rowB.x;
        const float px3 = pp ? rowB.w : rowB.y;

        float a0, b0, a1, b1, a2, b2, a3, b3;
        __sincosf(px0 * HPI, &b0, &a0);
        __sincosf(px1 * HPI, &b1, &a1);
        __sincosf(px2 * HPI, &b2, &a2);
        __sincosf(px3 * HPI, &b3, &a3);
        const float q01[4] = { a0 * a1, a0 * b1, b0 * a1, b0 * b1 };
        const float q23[4] = { a2 * a3, a2 * b3, b2 * a3, b2 * b3 };

        u32 ph[8], pl[8];
#pragma unroll
        for (int m = 0; m < 8; m++) {
            const float f01 = q01[m >> 1];
            const float lo = f01 * q23[(2 * m) & 3];
            const float hi = f01 * q23[(2 * m + 1) & 3];
            f16_split(lo, hi, ph[m], pl[m]);
        }

        uint4* slot = (uint4*)(ws + (2 * lane + pp) * 80);
        slot[0] = make_uint4(ph[0], ph[1], ph[2], ph[3]);
        slot[1] = make_uint4(ph[4], ph[5], ph[6], ph[7]);
        slot[2] = make_uint4(pl[0], pl[1], pl[2], pl[3]);
        slot[3] = make_uint4(pl[4], pl[5], pl[6], pl[7]);
    }
    __syncwarp();

    // ---- Z-matrix B fragment (fp16 ±1) ----
    u32 Bz[2];
    {
        const u32 s0 = ((2 * t)     >> (3 - (g & 3))) & 1 ? 0xBC00u : 0x3C00u;
        const u32 s1 = ((2 * t + 1) >> (3 - (g & 3))) & 1 ? 0xBC00u : 0x3C00u;
        const u32 s2 = ((2 * t + 8) >> (3 - (g & 3))) & 1 ? 0xBC00u : 0x3C00u;
        const u32 s3 = ((2 * t + 9) >> (3 - (g & 3))) & 1 ? 0xBC00u : 0x3C00u;
        Bz[0] = s0 | (s1 << 16);
        Bz[1] = s2 | (s3 << 16);
        if (g >= 4) { Bz[0] = 0u; Bz[1] = 0u; }
    }

    // ---- U B-fragments ----
    u32 Bhr[2][2], Bhi[2][2], Blr[2][2], Bli[2][2];
    {
        const uint4* bfv = ((const uint4*)g_Bfrag) + lane * 4;
        const uint4 vhr = bfv[0], vhi = bfv[1], vlr = bfv[2], vli = bfv[3];
        Bhr[0][0] = vhr.x; Bhr[0][1] = vhr.y; Bhr[1][0] = vhr.z; Bhr[1][1] = vhr.w;
        Bhi[0][0] = vhi.x; Bhi[0][1] = vhi.y; Bhi[1][0] = vhi.z; Bhi[1][1] = vhi.w;
        Blr[0][0] = vlr.x; Blr[0][1] = vlr.y; Blr[1][0] = vlr.z; Blr[1][1] = vlr.w;
        Bli[0][0] = vli.x; Bli[0][1] = vli.y; Bli[1][0] = vli.z; Bli[1][1] = vli.w;
    }

    const u32 wsa  = (u32)__cvta_generic_to_shared(ws);
    const u32 rowa = wsa + (u32)((lane & 15) * 80 + (lane >> 4) * 16);

#pragma unroll
    for (int T = 0; T < 4; T++) {
        u32 Aph[4], Apl[4];
        ldsm_x4(Aph, rowa + T * 16 * 80);
        ldsm_x4(Apl, rowa + T * 16 * 80 + 32);

        float Cr[2][4], Ci[2][4];
#pragma unroll
        for (int nt = 0; nt < 2; nt++)
#pragma unroll
            for (int k = 0; k < 4; k++) { Cr[nt][k] = 0.0f; Ci[nt][k] = 0.0f; }

#pragma unroll
        for (int nt = 0; nt < 2; nt++) {
            mma_f16(Cr[nt], Aph, Bhr[nt]);
            mma_f16(Cr[nt], Apl, Bhr[nt]);
            mma_f16(Cr[nt], Aph, Blr[nt]);
            mma_f16(Ci[nt], Aph, Bhi[nt]);
            mma_f16(Ci[nt], Apl, Bhi[nt]);
            mma_f16(Ci[nt], Aph, Bli[nt]);
        }

        // probs = |y|^2 -> fp16 A fragment -> single Z MMA
        float pr[2][4];
#pragma unroll
        for (int nt = 0; nt < 2; nt++)
#pragma unroll
            for (int k = 0; k < 4; k++)
                pr[nt][k] = fmaf(Cr[nt][k], Cr[nt][k], Ci[nt][k] * Ci[nt][k]);

        u32 Ap[4];
        Ap[0] = pack_f16x2(pr[0][0], pr[0][1]);
        Ap[1] = pack_f16x2(pr[0][2], pr[0][3]);
        Ap[2] = pack_f16x2(pr[1][0], pr[1][1]);
        Ap[3] = pack_f16x2(pr[1][2], pr[1][3]);

        float E[4] = {0.0f, 0.0f, 0.0f, 0.0f};
        mma_f16(E, Ap, Bz);

        if (t < 2) {
            const int p0s = warpbase + T * 16 + g;
            const int p1s = p0s + 8;
            if (p0s < npatch) *(float2*)(out + 4 * p0s + 2 * t) = make_float2(E[0], E[1]);
            if (p1s < npatch) *(float2*)(out + 4 * p1s + 2 * t) = make_float2(E[2], E[3]);
        }
    }
}

extern "C" void kernel_launch(void* const* d_in, const int* in_sizes, int n_in,
                              void* d_out, int out_size) {
    const float* x      = (const float*)d_in[0];
    const float* params = (const float*)d_in[1];
    float* out = (float*)d_out;

    const int bsz    = in_sizes[0] / 784;
    const int npatch = bsz * 196;

    build_U_kernel<<<1, 32>>>(params);

    const int blocks = (npatch + 511) / 512;
    quanv_kernel<<<blocks, 256>>>(x, out, npatch);
}

// round 10
// speedup vs baseline: 1.1218x; 1.1218x over previous
#include <cuda_runtime.h>
#include <cuda_fp16.h>

#define NQ 4
#define DIM 16
#define NPARAMS 36

typedef unsigned int u32;

// ---------------- helpers ----------------
__device__ __forceinline__ u32 pack_f16x2(float lo, float hi) {
    const __half2 h2 = __floats2half2_rn(lo, hi);
    return *(const u32*)&h2;
}
__device__ __forceinline__ void f16_split(float lo, float hi, u32& h, u32& l) {
    const __half2 h2 = __floats2half2_rn(lo, hi);
    const float2 f = __half22float2(h2);
    const __half2 l2 = __floats2half2_rn(lo - f.x, hi - f.y);
    h = *(const u32*)&h2;
    l = *(const u32*)&l2;
}
__device__ __forceinline__ void mma_f16(float c[4], const u32 a[4], const u32 b[2]) {
    asm volatile(
        "mma.sync.aligned.m16n8k16.row.col.f32.f16.f16.f32 "
        "{%0,%1,%2,%3}, {%4,%5,%6,%7}, {%8,%9}, {%0,%1,%2,%3};"
        : "+f"(c[0]), "+f"(c[1]), "+f"(c[2]), "+f"(c[3])
        : "r"(a[0]), "r"(a[1]), "r"(a[2]), "r"(a[3]), "r"(b[0]), "r"(b[1]));
}
__device__ __forceinline__ void ldsm_x4(u32 r[4], u32 saddr) {
    asm volatile("ldmatrix.sync.aligned.m8n8.x4.shared.b16 {%0,%1,%2,%3}, [%4];"
                 : "=r"(r[0]), "=r"(r[1]), "=r"(r[2]), "=r"(r[3]) : "r"(saddr));
}

// ---------------------------------------------------------------------------
// Single fused kernel.
//   Warp 0 prologue: build U(params) in SMEM (fp32), pack fp16-split B-frags.
//   All warps:       R7 front phase (pixels -> psi0 -> fp16 split -> stage).
//   __syncthreads, then 4-tile MMA loop identical to R7.
// ---------------------------------------------------------------------------
__global__ void __launch_bounds__(256) quanv_kernel(
    const float* __restrict__ x, const float* __restrict__ params,
    float* __restrict__ out, int npatch)
{
    __shared__ __align__(16) unsigned char stage[8 * 64 * 80];  // 40960 B
    __shared__ float sUr[DIM][DIM];       // U real, [row][col]
    __shared__ float sUi[DIM][DIM];       // U imag
    __shared__ __align__(16) float sCoef[12][4];
    __shared__ __align__(16) u32 sBfrag[32][20];  // 16 used, 80B stride

    const int tid  = threadIdx.x;
    const int lane = tid & 31;
    const int wrp  = tid >> 5;
    const int g    = lane >> 2;
    const int t    = lane & 3;

    const int warpbase = blockIdx.x * 512 + wrp * 64;
    unsigned char* const ws = stage + wrp * (64 * 80);

    const float HPI = 1.5707963267948966f;

    // ================= warp 0: build U =================
    if (wrp == 0) {
        // lanes 0..11: fused RY·RZ·RY coefficients for gate gi = lane
        if (lane < 12) {
            const float t1 = 0.5f * __ldg(&params[3 * lane]);
            const float t2 = 0.5f * __ldg(&params[3 * lane + 1]);
            const float t3 = 0.5f * __ldg(&params[3 * lane + 2]);
            float A, B_, C, D, cf, sf;
            __sincosf(t1 + t3, &B_, &A);
            __sincosf(t1 - t3, &D, &C);
            __sincosf(t2, &sf, &cf);
            float4 co;
            co.x = A * cf;   // p
            co.y = B_ * cf;  // q
            co.z = C * sf;   // u
            co.w = D * sf;   // w
            *(float4*)sCoef[lane] = co;
        }
        __syncwarp();

        // lanes 0..15: evolve column c in SMEM
        if (lane < 16) {
            const int c = lane;
#pragma unroll
            for (int r = 0; r < DIM; r++) {
                sUr[r][c] = (r == c) ? 1.0f : 0.0f;
                sUi[r][c] = 0.0f;
            }
            int gi = 0;
#pragma unroll
            for (int layer = 0; layer < 3; layer++) {
#pragma unroll
                for (int wi = 0; wi < NQ; wi++) {
                    const int bit = 1 << (NQ - 1 - wi);
                    const float4 co = *(const float4*)sCoef[gi]; gi++;
                    const float p = co.x, q = co.y, u = co.z, w = co.w;
#pragma unroll
                    for (int r = 0; r < DIM; r++) {
                        if (r & bit) continue;
                        const int r1 = r | bit;
                        const float v0r = sUr[r][c],  v0i = sUi[r][c];
                        const float v1r = sUr[r1][c], v1i = sUi[r1][c];
                        sUr[r][c]  =  p * v0r + u * v0i - q * v1r - w * v1i;
                        sUi[r][c]  = -u * v0r + p * v0i + w * v1r - q * v1i;
                        sUr[r1][c] =  q * v0r - w * v0i + p * v1r - u * v1i;
                        sUi[r1][c] =  w * v0r + q * v0i + u * v1r + p * v1i;
                    }
                }
                // CNOT ring = row swaps
#pragma unroll
                for (int gg = 0; gg < NQ; gg++) {
                    const int cb = 1 << (NQ - 1 - gg);
                    const int tb = 1 << (NQ - 1 - ((gg + 1) & 3));
#pragma unroll
                    for (int r = 0; r < DIM; r++) {
                        if ((r & cb) && !(r & tb)) {
                            const int r1 = r | tb;
                            float tmp;
                            tmp = sUr[r][c]; sUr[r][c] = sUr[r1][c]; sUr[r1][c] = tmp;
                            tmp = sUi[r][c]; sUi[r][c] = sUi[r1][c]; sUi[r1][c] = tmp;
                        }
                    }
                }
            }
        }
        __syncwarp();

        // all 32 lanes: pack this lane's B fragments (fp16 split) into sBfrag
        {
            u32 frag[16];
#pragma unroll
            for (int nt = 0; nt < 2; nt++) {
                const int kk = 8 * nt + g;
                f16_split(sUr[kk][2 * t],     sUr[kk][2 * t + 1], frag[0 + 2 * nt], frag[8  + 2 * nt]);
                f16_split(sUr[kk][2 * t + 8], sUr[kk][2 * t + 9], frag[1 + 2 * nt], frag[9  + 2 * nt]);
                f16_split(sUi[kk][2 * t],     sUi[kk][2 * t + 1], frag[4 + 2 * nt], frag[12 + 2 * nt]);
                f16_split(sUi[kk][2 * t + 8], sUi[kk][2 * t + 9], frag[5 + 2 * nt], frag[13 + 2 * nt]);
            }
            uint4* dst = (uint4*)sBfrag[lane];
#pragma unroll
            for (int v = 0; v < 4; v++)
                dst[v] = make_uint4(frag[4 * v], frag[4 * v + 1], frag[4 * v + 2], frag[4 * v + 3]);
        }
    }

    // ================= all warps: front phase (R7) =================
    const float* basep[2];
#pragma unroll
    for (int pp = 0; pp < 2; pp++) {
        const int p  = warpbase + pp * 32 + lane;
        const int pc = (p < npatch) ? p : (npatch - 1);
        const int b  = pc / 196;
        const int q  = pc - b * 196;
        const int r  = q / 14;
        const int cc = q - r * 14;
        basep[pp] = x + b * 784 + r * 56 + cc * 2;
    }
    float2 V01[2], V23[2];
#pragma unroll
    for (int pp = 0; pp < 2; pp++) {
        V01[pp] = *(const float2*)(basep[pp]);
        V23[pp] = *(const float2*)(basep[pp] + 28);
    }

#pragma unroll
    for (int pp = 0; pp < 2; pp++) {
        float a0, b0, a1, b1, a2, b2, a3, b3;
        __sincosf(V01[pp].x * HPI, &b0, &a0);
        __sincosf(V01[pp].y * HPI, &b1, &a1);
        __sincosf(V23[pp].x * HPI, &b2, &a2);
        __sincosf(V23[pp].y * HPI, &b3, &a3);
        const float q01[4] = { a0 * a1, a0 * b1, b0 * a1, b0 * b1 };
        const float q23[4] = { a2 * a3, a2 * b3, b2 * a3, b2 * b3 };

        u32 ph[8], pl[8];
#pragma unroll
        for (int m = 0; m < 8; m++) {
            const float f01 = q01[m >> 1];
            const float lo = f01 * q23[(2 * m) & 3];
            const float hi = f01 * q23[(2 * m + 1) & 3];
            f16_split(lo, hi, ph[m], pl[m]);
        }

        uint4* slot = (uint4*)(ws + (pp * 32 + lane) * 80);
        slot[0] = make_uint4(ph[0], ph[1], ph[2], ph[3]);
        slot[1] = make_uint4(ph[4], ph[5], ph[6], ph[7]);
        slot[2] = make_uint4(pl[0], pl[1], pl[2], pl[3]);
        slot[3] = make_uint4(pl[4], pl[5], pl[6], pl[7]);
    }

    // ---- Z-matrix B fragment (fp16 ±1) ----
    u32 Bz[2];
    {
        const u32 s0 = ((2 * t)     >> (3 - (g & 3))) & 1 ? 0xBC00u : 0x3C00u;
        const u32 s1 = ((2 * t + 1) >> (3 - (g & 3))) & 1 ? 0xBC00u : 0x3C00u;
        const u32 s2 = ((2 * t + 8) >> (3 - (g & 3))) & 1 ? 0xBC00u : 0x3C00u;
        const u32 s3 = ((2 * t + 9) >> (3 - (g & 3))) & 1 ? 0xBC00u : 0x3C00u;
        Bz[0] = s0 | (s1 << 16);
        Bz[1] = s2 | (s3 << 16);
        if (g >= 4) { Bz[0] = 0u; Bz[1] = 0u; }
    }

    __syncthreads();   // staging + sBfrag visible

    // ---- U B-fragments from SMEM (conflict-free LDS.128, 80B stride) ----
    u32 Bhr[2][2], Bhi[2][2], Blr[2][2], Bli[2][2];
    {
        const uint4* bfv = (const uint4*)sBfrag[lane];
        const uint4 vhr = bfv[0], vhi = bfv[1], vlr = bfv[2], vli = bfv[3];
        Bhr[0][0] = vhr.x; Bhr[0][1] = vhr.y; Bhr[1][0] = vhr.z; Bhr[1][1] = vhr.w;
        Bhi[0][0] = vhi.x; Bhi[0][1] = vhi.y; Bhi[1][0] = vhi.z; Bhi[1][1] = vhi.w;
        Blr[0][0] = vlr.x; Blr[0][1] = vlr.y; Blr[1][0] = vlr.z; Blr[1][1] = vlr.w;
        Bli[0][0] = vli.x; Bli[0][1] = vli.y; Bli[1][0] = vli.z; Bli[1][1] = vli.w;
    }

    const u32 wsa  = (u32)__cvta_generic_to_shared(ws);
    const u32 rowa = wsa + (u32)((lane & 15) * 80 + (lane >> 4) * 16);

#pragma unroll
    for (int T = 0; T < 4; T++) {
        u32 Aph[4], Apl[4];
        ldsm_x4(Aph, rowa + T * 16 * 80);
        ldsm_x4(Apl, rowa + T * 16 * 80 + 32);

        float Cr[2][4], Ci[2][4];
#pragma unroll
        for (int nt = 0; nt < 2; nt++)
#pragma unroll
            for (int k = 0; k < 4; k++) { Cr[nt][k] = 0.0f; Ci[nt][k] = 0.0f; }

#pragma unroll
        for (int nt = 0; nt < 2; nt++) {
            mma_f16(Cr[nt], Aph, Bhr[nt]);
            mma_f16(Cr[nt], Apl, Bhr[nt]);
            mma_f16(Cr[nt], Aph, Blr[nt]);
            mma_f16(Ci[nt], Aph, Bhi[nt]);
            mma_f16(Ci[nt], Apl, Bhi[nt]);
            mma_f16(Ci[nt], Aph, Bli[nt]);
        }

        // probs = |y|^2 -> fp16 A fragment -> single Z MMA
        float pr[2][4];
#pragma unroll
        for (int nt = 0; nt < 2; nt++)
#pragma unroll
            for (int k = 0; k < 4; k++)
                pr[nt][k] = fmaf(Cr[nt][k], Cr[nt][k], Ci[nt][k] * Ci[nt][k]);

        u32 Ap[4];
        Ap[0] = pack_f16x2(pr[0][0], pr[0][1]);
        Ap[1] = pack_f16x2(pr[0][2], pr[0][3]);
        Ap[2] = pack_f16x2(pr[1][0], pr[1][1]);
        Ap[3] = pack_f16x2(pr[1][2], pr[1][3]);

        float E[4] = {0.0f, 0.0f, 0.0f, 0.0f};
        mma_f16(E, Ap, Bz);

        if (t < 2) {
            const int p0s = warpbase + T * 16 + g;
            const int p1s = p0s + 8;
            if (p0s < npatch) *(float2*)(out + 4 * p0s + 2 * t) = make_float2(E[0], E[1]);
            if (p1s < npatch) *(float2*)(out + 4 * p1s + 2 * t) = make_float2(E[2], E[3]);
        }
    }
}

extern "C" void kernel_launch(void* const* d_in, const int* in_sizes, int n_in,
                              void* d_out, int out_size) {
    const float* x      = (const float*)d_in[0];
    const float* params = (const float*)d_in[1];
    float* out = (float*)d_out;

    const int bsz    = in_sizes[0] / 784;
    const int npatch = bsz * 196;

    const int blocks = (npatch + 511) / 512;
    quanv_kernel<<<blocks, 256>>>(x, params, out, npatch);
}